// round 1
// baseline (speedup 1.0000x reference)
#include <cuda_runtime.h>
#include <cstdint>

// Focal CTC loss, fused single-pass implementation.
//   - one CTA per batch sample b (grid = B)
//   - one thread per extended-label state s (S = 2L+1 = 201 <= 256 threads)
//   - alpha recursion in log2 domain, double-buffered in shared memory
//   - log_probs rows streamed via cp.async 4-deep ring (each row read ONCE)
//   - sum_t exp(log_probs[t,b,c]) fused into the same pass (register per thread)
//   - final scalar = mean(loss) * mean(focal_weight)   [outer-product mean factorizes]

#define CFIX   256           // C is fixed to 256 for this problem (== blockDim)
#define SPAD   260           // >= S + 2 pad + slack for garbage lanes (2+255 = 257)
#define DEPTH  4
#define NEG2   (-1e30f)
#define LOG2E  1.4426950408889634f
#define LN2    0.6931471805599453f

__device__ float g_loss[1024];
__device__ float g_wsum[1024];

__device__ __forceinline__ float ex2f(float x) {
    float y; asm("ex2.approx.ftz.f32 %0, %1;" : "=f"(y) : "f"(x)); return y;
}
__device__ __forceinline__ float lg2f(float x) {
    float y; asm("lg2.approx.ftz.f32 %0, %1;" : "=f"(y) : "f"(x)); return y;
}

__global__ __launch_bounds__(256, 1)
void focal_ctc_kernel(const float* __restrict__ lp,      // (T,B,C)
                      const int*   __restrict__ targets, // (B*L)
                      const int*   __restrict__ in_len,  // (B)
                      const int*   __restrict__ tg_len,  // (B)
                      int T, int B, int L)
{
    __shared__ float ring[DEPTH][CFIX];   // log_probs row ring
    __shared__ float abuf[2][SPAD];       // alpha double buffer, 2-elem NEG pad at front
    __shared__ float sums[CFIX];          // per-channel exp sums (epilogue)
    __shared__ float lastv[2];            // alpha at (len-1) for states 2*tl, 2*tl-1
    __shared__ float red[CFIX];           // focal-weight reduction scratch

    const int b   = blockIdx.x;
    const int tid = threadIdx.x;
    const int S   = 2 * L + 1;
    const int len = in_len[b];
    const int tl  = tg_len[b];

    // --- per-thread static state: extended symbol + skip-transition mask ---
    int  extS   = 0;
    bool isState = (tid < S);
    bool allow2  = false;
    if (isState) {
        if (tid & 1) extS = targets[b * L + (tid >> 1)];
        if (tid >= 2 && extS != 0) {
            int extPrev = ((tid - 2) & 1) ? targets[b * L + ((tid - 2) >> 1)] : 0;
            allow2 = (extS != extPrev);
        }
    }
    // front pads so alpha[s-1], alpha[s-2] reads never branch
    if (tid < 2) { abuf[0][tid] = NEG2; abuf[1][tid] = NEG2; }

    const float* rowbase = lp + (size_t)b * CFIX;      // + t*B*C + tid
    const size_t tstride = (size_t)B * CFIX;

    // --- prologue: issue rows 0..2 into ring slots 0..2 (one group per row) ---
    {
        const float* src = rowbase + tid;
        #pragma unroll
        for (int r = 0; r < DEPTH - 1; r++) {
            uint32_t dst = (uint32_t)__cvta_generic_to_shared(&ring[r][tid]);
            asm volatile("cp.async.ca.shared.global [%0], [%1], 4;"
                         :: "r"(dst), "l"(src) : "memory");
            asm volatile("cp.async.commit_group;" ::: "memory");
            src += tstride;
        }
    }

    float a0   = NEG2;   // this thread's own alpha (previous step), in log2 domain
    float sExp = 0.0f;   // sum over t of exp(log_probs[t,b,tid])
    int   cur  = 0;

    const float* srcNext = rowbase + (size_t)(DEPTH - 1) * tstride + tid;

    for (int t = 0; t < T; ++t) {
        // groups committed so far = 3 + t (rows 0..t+2); keep newest 2 pending
        asm volatile("cp.async.wait_group 2;" ::: "memory");
        __syncthreads();   // row t visible to all; alpha writes of t-1 visible

        const int slot = t & (DEPTH - 1);
        float rraw = ring[slot][extS];   // emission log-prob (natural log)
        float rown = ring[slot][tid];    // this thread's channel, for exp-sum
        sExp += ex2f(rown * LOG2E);

        float newv;
        if (t == 0) {
            newv = (tid < 2) ? rraw * LOG2E : NEG2;
        } else {
            const float* prev = abuf[cur ^ 1];
            float a1 = prev[1 + tid];                   // alpha[s-1] (pad -> NEG)
            float a2 = allow2 ? prev[tid] : NEG2;       // alpha[s-2]
            float m  = fmaxf(a0, fmaxf(a1, a2));
            float ss = ex2f(a0 - m) + ex2f(a1 - m) + ex2f(a2 - m);
            newv = fmaf(rraw, LOG2E, m + lg2f(ss));
        }
        abuf[cur][2 + tid] = newv;   // all 256 threads write; lanes >= S hold ~NEG2
        a0 = newv;

        if (t == len - 1 && isState) {
            if (tid == 2 * tl)     lastv[0] = newv;
            if (tid == 2 * tl - 1) lastv[1] = newv;
        }

        // issue row t+3 into slot (t+3)&3 == (t-1)&3 (safe: all reads of row
        // t-1 completed before this iteration's barrier). Always commit one
        // group per iteration so wait_group counts stay exact at the tail.
        if (t + DEPTH - 1 < T) {
            uint32_t dst = (uint32_t)__cvta_generic_to_shared(
                &ring[(t + DEPTH - 1) & (DEPTH - 1)][tid]);
            asm volatile("cp.async.ca.shared.global [%0], [%1], 4;"
                         :: "r"(dst), "l"(srcNext) : "memory");
            srcNext += tstride;
        }
        asm volatile("cp.async.commit_group;" ::: "memory");
        cur ^= 1;
    }

    asm volatile("cp.async.wait_group 0;" ::: "memory");
    __syncthreads();

    // --- epilogue: focal weights + per-sample loss ---
    sums[tid] = sExp;
    __syncthreads();

    float w = 0.0f;
    if (tid < L) {
        int   c  = targets[b * L + tid];
        float p  = sums[c] * (1.0f / (float)T);   // mean over T of exp(log_prob)
        float om = 1.0f - p;
        w = om * om;                               // GAMMA = 2
    }
    red[tid] = w;
    __syncthreads();

    if (tid == 0) {
        float ws = 0.0f;
        for (int i = 0; i < L; i++) ws += red[i];
        float la = lastv[0], lb = lastv[1];
        float m  = fmaxf(la, lb);
        float ll2 = m + lg2f(ex2f(la - m) + ex2f(lb - m));
        float ll  = ll2 * LN2;                     // back to natural log
        float loss = (ll > -5e29f) ? -ll : 0.0f;   // zero_infinity semantics
        g_loss[b] = loss;
        g_wsum[b] = ws;
    }
}

__global__ void finalize_kernel(float* __restrict__ out, int B, int L)
{
    if (threadIdx.x == 0 && blockIdx.x == 0) {
        float ls = 0.0f, ws = 0.0f;
        for (int i = 0; i < B; i++) { ls += g_loss[i]; ws += g_wsum[i]; }
        // mean over (B, B*L) outer product == mean(loss) * mean(focal_weight)
        out[0] = (ls / (float)B) * (ws / ((float)B * (float)L));
    }
}

extern "C" void kernel_launch(void* const* d_in, const int* in_sizes, int n_in,
                              void* d_out, int out_size)
{
    const float* lp      = (const float*)d_in[0];
    const int*   targets = (const int*)d_in[1];
    const int*   in_len  = (const int*)d_in[2];
    const int*   tg_len  = (const int*)d_in[3];

    int B = in_sizes[2];                 // 64
    int L = in_sizes[1] / B;             // 100
    int T = in_sizes[0] / (B * CFIX);    // 1000 (C fixed at 256)

    focal_ctc_kernel<<<B, 256>>>(lp, targets, in_len, tg_len, T, B, L);
    finalize_kernel<<<1, 32>>>((float*)d_out, B, L);
}